// round 1
// baseline (speedup 1.0000x reference)
#include <cuda_runtime.h>
#include <cstdint>
#include <cstddef>

#define DIN 128
#define NA  64
#define EDIM 32

// packed fp32x2 FMA (Blackwell FFMA2): d.lo=a.lo*b.lo+c.lo, d.hi=a.hi*b.hi+c.hi
__device__ __forceinline__ unsigned long long ffma2(unsigned long long a,
                                                    unsigned long long b,
                                                    unsigned long long c) {
    unsigned long long d;
    asm("fma.rn.f32x2 %0, %1, %2, %3;" : "=l"(d) : "l"(a), "l"(b), "l"(c));
    return d;
}
__device__ __forceinline__ float2 unpk(unsigned long long v) {
    float2 f;
    asm("mov.b64 {%0, %1}, %2;" : "=f"(f.x), "=f"(f.y) : "l"(v));
    return f;
}

__global__ void __launch_bounds__(256, 4) attn_kernel(
    const float* __restrict__ X, const float* __restrict__ W1,
    const float* __restrict__ b1, const float* __restrict__ C,
    const float* __restrict__ W2, const float* __restrict__ b2,
    float* __restrict__ out)
{
    // fi[64][36]  : row-major, pad 36 (36 mod 32 = 4 -> conflict-free LDS.128 across rows)
    // sW[64][68]  : alpha (softmax weights), pad 68
    // sU          : phase A = W1^T [32][132]; phase B = C^T [32][36] + g [64][36]
    __shared__ __align__(16) float sFi[NA * 36];
    __shared__ __align__(16) float sW [NA * 68];
    __shared__ __align__(16) float sU [32 * 132];
    __shared__ float sB1[EDIM];
    __shared__ float sW2[2 * EDIM];
    __shared__ float sB2;

    const int tid = threadIdx.x;
    const int wrp = tid >> 5;
    const int l   = tid & 31;
    const int b   = blockIdx.x;
    const int i0  = wrp * 8;          // this warp owns rows i0..i0+7 throughout

    // ---- load W1 transposed (W1T[e][k]), biases, W2 ----
    for (int idx = tid; idx < DIN * EDIM; idx += 256) {
        int k = idx >> 5, e = idx & 31;
        sU[e * 132 + k] = W1[idx];
    }
    if (tid < EDIM)     sB1[tid] = b1[tid];
    if (tid < 2 * EDIM) sW2[tid] = W2[tid];
    if (tid == 0)       sB2 = b2[0];
    __syncthreads();

    // ---- phase A: fi = relu(X @ W1 + b1) ----
    // warp: 8 rows, lane = e. k-pairs packed into f32x2 (operands naturally contiguous).
    {
        unsigned long long acc[8];
        #pragma unroll
        for (int r = 0; r < 8; r++) acc[r] = 0ull;
        const float* xb = X + ((size_t)b * NA + i0) * DIN;
        #pragma unroll 2
        for (int k4 = 0; k4 < 32; k4++) {
            ulonglong2 wv = *(const ulonglong2*)(sU + l * 132 + k4 * 4);
            #pragma unroll
            for (int r = 0; r < 8; r++) {
                ulonglong2 xv = *(const ulonglong2*)(xb + r * DIN + k4 * 4); // warp-broadcast LDG.128
                acc[r] = ffma2(xv.x, wv.x, acc[r]);
                acc[r] = ffma2(xv.y, wv.y, acc[r]);
            }
        }
        #pragma unroll
        for (int r = 0; r < 8; r++) {
            float2 p = unpk(acc[r]);
            sFi[(i0 + r) * 36 + l] = fmaxf(p.x + p.y + sB1[l], 0.0f);
        }
    }
    __syncthreads();   // fi visible to all warps; W1T dead

    // ---- load C transposed into sU (CT[f][e]) ----
    for (int idx = tid; idx < EDIM * EDIM; idx += 256) {
        int e = idx >> 5, f = idx & 31;
        sU[f * 36 + e] = C[idx];
    }
    __syncthreads();

    float* sCT = sU;                 // 32*36 floats
    float* sG  = sU + EDIM * 36;     // 64*36 floats

    // ---- g = fi @ C  (lane = f, e-pairs packed) ----
    {
        unsigned long long ga[8];
        #pragma unroll
        for (int r = 0; r < 8; r++) ga[r] = 0ull;
        #pragma unroll
        for (int e4 = 0; e4 < 8; e4++) {
            ulonglong2 cv = *(const ulonglong2*)(sCT + l * 36 + e4 * 4);
            #pragma unroll
            for (int r = 0; r < 8; r++) {
                ulonglong2 fv = *(const ulonglong2*)(sFi + (i0 + r) * 36 + e4 * 4);
                ga[r] = ffma2(fv.x, cv.x, ga[r]);
                ga[r] = ffma2(fv.y, cv.y, ga[r]);
            }
        }
        #pragma unroll
        for (int r = 0; r < 8; r++) {
            float2 p = unpk(ga[r]);
            sG[(i0 + r) * 36 + l] = p.x + p.y;
        }
    }
    __syncwarp();   // g rows read only by the warp that wrote them

    // ---- beta = g @ fi^T, diag mask, softmax -> alpha in sW ----
    // lane covers j = l and j = l+32; 4 rows at a time for fi-load reuse.
    #pragma unroll
    for (int gi = 0; gi < 2; gi++) {
        const int ib = i0 + gi * 4;
        unsigned long long bl[4], bh[4];
        #pragma unroll
        for (int r = 0; r < 4; r++) { bl[r] = 0ull; bh[r] = 0ull; }
        #pragma unroll
        for (int e4 = 0; e4 < 8; e4++) {
            ulonglong2 fl = *(const ulonglong2*)(sFi + l * 36 + e4 * 4);
            ulonglong2 fh = *(const ulonglong2*)(sFi + (l + 32) * 36 + e4 * 4);
            #pragma unroll
            for (int r = 0; r < 4; r++) {
                ulonglong2 gv = *(const ulonglong2*)(sG + (ib + r) * 36 + e4 * 4);
                bl[r] = ffma2(gv.x, fl.x, bl[r]);
                bl[r] = ffma2(gv.y, fl.y, bl[r]);
                bh[r] = ffma2(gv.x, fh.x, bh[r]);
                bh[r] = ffma2(gv.y, fh.y, bh[r]);
            }
        }
        #pragma unroll
        for (int r = 0; r < 4; r++) {
            const int i = ib + r;
            float2 pl = unpk(bl[r]), ph = unpk(bh[r]);
            float blo = pl.x + pl.y;
            float bhi = ph.x + ph.y;
            if (l == i)      blo = -3.0e38f;   // diagonal -> -inf
            if (l + 32 == i) bhi = -3.0e38f;
            float m = fmaxf(blo, bhi);
            #pragma unroll
            for (int s = 16; s > 0; s >>= 1)
                m = fmaxf(m, __shfl_xor_sync(0xffffffffu, m, s));
            float elo = __expf(blo - m);
            float ehi = __expf(bhi - m);
            float z = elo + ehi;
            #pragma unroll
            for (int s = 16; s > 0; s >>= 1)
                z += __shfl_xor_sync(0xffffffffu, z, s);
            float rz = __fdividef(1.0f, z);
            sW[i * 68 + l]      = elo * rz;
            sW[i * 68 + l + 32] = ehi * rz;
        }
    }
    __syncwarp();   // alpha rows read only within this warp

    // ---- v = alpha @ fi  (lane = e), then fc2 + sigmoid ----
    {
        float vac[8];
        #pragma unroll
        for (int r = 0; r < 8; r++) vac[r] = 0.0f;
        #pragma unroll 2
        for (int j4 = 0; j4 < 16; j4++) {
            float f0 = sFi[(j4 * 4 + 0) * 36 + l];
            float f1 = sFi[(j4 * 4 + 1) * 36 + l];
            float f2 = sFi[(j4 * 4 + 2) * 36 + l];
            float f3 = sFi[(j4 * 4 + 3) * 36 + l];
            #pragma unroll
            for (int r = 0; r < 8; r++) {
                float4 wv = *(const float4*)(sW + (i0 + r) * 68 + j4 * 4); // broadcast
                vac[r] = fmaf(wv.x, f0, vac[r]);
                vac[r] = fmaf(wv.y, f1, vac[r]);
                vac[r] = fmaf(wv.z, f2, vac[r]);
                vac[r] = fmaf(wv.w, f3, vac[r]);
            }
        }
        const float w2a = sW2[l];
        const float w2b = sW2[EDIM + l];
        #pragma unroll
        for (int r = 0; r < 8; r++) {
            const int i = i0 + r;
            float x = fmaf(sFi[i * 36 + l], w2a, vac[r] * w2b);
            #pragma unroll
            for (int s = 16; s > 0; s >>= 1)
                x += __shfl_xor_sync(0xffffffffu, x, s);
            if (l == 0)
                out[(size_t)b * NA + i] =
                    __fdividef(1.0f, 1.0f + __expf(-(x + sB2)));
        }
    }
}

extern "C" void kernel_launch(void* const* d_in, const int* in_sizes, int n_in,
                              void* d_out, int out_size) {
    const float* X  = (const float*)d_in[0];
    const float* W1 = (const float*)d_in[1];
    const float* b1 = (const float*)d_in[2];
    const float* C  = (const float*)d_in[3];
    const float* W2 = (const float*)d_in[4];
    const float* b2 = (const float*)d_in[5];
    float* out = (float*)d_out;

    const int rows    = in_sizes[0] / DIN;   // B*N
    const int batches = rows / NA;           // B
    attn_kernel<<<batches, 256>>>(X, W1, b1, C, W2, b2, out);
}

// round 4
// speedup vs baseline: 3.2811x; 3.2811x over previous
#include <cuda_runtime.h>
#include <cstdint>
#include <cstddef>

#define THREADS 256

// ---- shared layout (float offsets) ----
// Phase A region [0 .. 13440): sW1T [32][132] @0 ; sX0 [128][36] @4224 ; sX1 @8832
// Phase B alias : sAL [128][68] @0 ; sG [128][36] @8704
#define O_W1T 0
#define O_X0  4224
#define O_X1  8832
#define O_AL  0
#define O_G   8704
#define O_FI  13440   // [128][36]
#define O_FIT 18048   // [32][132]
#define O_CT  22272   // [32][36]
#define O_B1  23424
#define O_W2  23456
#define O_B2  23520
#define SMEM_FLOATS 23521
#define SMEM_BYTES  (SMEM_FLOATS * 4)

#define CP_ASYNC16(d, s) asm volatile("cp.async.cg.shared.global [%0], [%1], 16;" :: "r"(d), "l"(s))
#define CP_COMMIT()      asm volatile("cp.async.commit_group;")
#define CP_WAIT(n)       asm volatile("cp.async.wait_group %0;" :: "n"(n))

__device__ __forceinline__ uint32_t tf32u(float f) {
    uint32_t r; asm("cvt.rna.tf32.f32 %0, %1;" : "=r"(r) : "f"(f)); return r;
}
__device__ __forceinline__ float tf32f(float f) { return __uint_as_float(tf32u(f)); }
__device__ __forceinline__ uint32_t fau(float f) { return __float_as_uint(f); }

// D(16x8,f32) += A(16x8,tf32) * B(8x8,tf32)   [row.col: D[m,n] += sum_k A[m,k]*B[n,k]]
__device__ __forceinline__ void mma8(float* d, uint32_t a0, uint32_t a1, uint32_t a2, uint32_t a3,
                                     uint32_t b0, uint32_t b1) {
    asm("mma.sync.aligned.m16n8k8.row.col.f32.tf32.tf32.f32 "
        "{%0,%1,%2,%3}, {%4,%5,%6,%7}, {%8,%9}, {%0,%1,%2,%3};"
        : "+f"(d[0]), "+f"(d[1]), "+f"(d[2]), "+f"(d[3])
        : "r"(a0), "r"(a1), "r"(a2), "r"(a3), "r"(b0), "r"(b1));
}

__global__ void __launch_bounds__(THREADS, 2) attn_mma(
    const float* __restrict__ X, const float* __restrict__ W1,
    const float* __restrict__ b1, const float* __restrict__ C,
    const float* __restrict__ W2, const float* __restrict__ b2,
    float* __restrict__ out)
{
    extern __shared__ float sm[];
    const int tid = threadIdx.x;
    const int w   = tid >> 5;
    const int l   = tid & 31;
    const int g   = l >> 2;        // group row 0..7
    const int tq  = l & 3;         // thread-in-group 0..3
    const int m0  = w * 16;        // warp's 16 rows
    const int bt  = w >> 2;        // batch within CTA (0/1)
    const int rl  = m0 + g, rh = rl + 8;
    const size_t r0 = (size_t)blockIdx.x * 128;

    const float* Xg = X + r0 * 128;

    // ---- prefetch X k-chunks (K=32 each) via cp.async ----
    const int prow = tid >> 3;       // 0..31
    const int pc8  = tid & 7;        // 16B column group
    auto prefetch = [&](int c, int xoff) {
        #pragma unroll
        for (int p = 0; p < 4; p++) {
            int row = prow + p * 32;
            uint32_t dst = (uint32_t)__cvta_generic_to_shared(sm + xoff + row * 36 + pc8 * 4);
            CP_ASYNC16(dst, Xg + (size_t)row * 128 + c * 32 + pc8 * 4);
        }
        CP_COMMIT();
    };
    prefetch(0, O_X0);
    prefetch(1, O_X1);

    // ---- stage W1^T [e][k] (tf32), C^T [f][e] (tf32), biases, W2 ----
    for (int idx = tid; idx < 4096; idx += THREADS) {
        int e = idx >> 7, k = idx & 127;
        sm[O_W1T + e * 132 + k] = tf32f(W1[k * 32 + e]);
    }
    for (int idx = tid; idx < 1024; idx += THREADS) {
        int f = idx >> 5, e = idx & 31;
        sm[O_CT + f * 36 + e] = tf32f(C[e * 32 + f]);
    }
    if (tid < 32) sm[O_B1 + tid] = b1[tid];
    if (tid < 64) sm[O_W2 + tid] = W2[tid];
    if (tid == 0) sm[O_B2] = b2[0];

    // ================= fc1: acc = X @ W1 =================
    float acc[4][4];
    #pragma unroll
    for (int n = 0; n < 4; n++)
        #pragma unroll
        for (int c = 0; c < 4; c++) acc[n][c] = 0.0f;

    auto fc1_chunk = [&](int c, int xoff) {
        const float* Xb = sm + xoff;
        #pragma unroll
        for (int ks = 0; ks < 4; ks++) {
            int klo = ks * 8, kgl = c * 32 + klo;
            uint32_t A0 = tf32u(Xb[rl * 36 + klo + tq]);
            uint32_t A2 = tf32u(Xb[rl * 36 + klo + tq + 4]);
            uint32_t A1 = tf32u(Xb[rh * 36 + klo + tq]);
            uint32_t A3 = tf32u(Xb[rh * 36 + klo + tq + 4]);
            #pragma unroll
            for (int n = 0; n < 4; n++) {
                uint32_t B0 = fau(sm[O_W1T + (8 * n + g) * 132 + kgl + tq]);
                uint32_t B1 = fau(sm[O_W1T + (8 * n + g) * 132 + kgl + tq + 4]);
                mma8(acc[n], A0, A1, A2, A3, B0, B1);
            }
        }
    };

    CP_WAIT(1); __syncthreads();
    fc1_chunk(0, O_X0);
    __syncthreads();
    prefetch(2, O_X0);
    CP_WAIT(1); __syncthreads();
    fc1_chunk(1, O_X1);
    __syncthreads();
    prefetch(3, O_X1);
    CP_WAIT(1); __syncthreads();
    fc1_chunk(2, O_X0);
    CP_WAIT(0); __syncthreads();
    fc1_chunk(3, O_X1);

    // ---- epilogue: fi = relu(acc + b1) -> sFI [i][e], sFIT [e][i] (tf32) ----
    #pragma unroll
    for (int n = 0; n < 4; n++) {
        int e0 = 8 * n + 2 * tq;
        float q00 = tf32f(fmaxf(acc[n][0] + sm[O_B1 + e0],     0.0f));
        float q01 = tf32f(fmaxf(acc[n][1] + sm[O_B1 + e0 + 1], 0.0f));
        float q10 = tf32f(fmaxf(acc[n][2] + sm[O_B1 + e0],     0.0f));
        float q11 = tf32f(fmaxf(acc[n][3] + sm[O_B1 + e0 + 1], 0.0f));
        sm[O_FI + rl * 36 + e0]     = q00;
        sm[O_FI + rl * 36 + e0 + 1] = q01;
        sm[O_FI + rh * 36 + e0]     = q10;
        sm[O_FI + rh * 36 + e0 + 1] = q11;
        sm[O_FIT + e0 * 132 + rl]       = q00;
        sm[O_FIT + (e0 + 1) * 132 + rl] = q01;
        sm[O_FIT + e0 * 132 + rh]       = q10;
        sm[O_FIT + (e0 + 1) * 132 + rh] = q11;
    }
    __syncthreads();   // fi/fiT visible; phase-A region now dead -> reuse for g/alpha

    // ================= g = fi @ C =================
    float ag[4][4];
    #pragma unroll
    for (int n = 0; n < 4; n++)
        #pragma unroll
        for (int c = 0; c < 4; c++) ag[n][c] = 0.0f;
    #pragma unroll
    for (int ks = 0; ks < 4; ks++) {
        uint32_t A0 = fau(sm[O_FI + rl * 36 + 8 * ks + tq]);
        uint32_t A2 = fau(sm[O_FI + rl * 36 + 8 * ks + tq + 4]);
        uint32_t A1 = fau(sm[O_FI + rh * 36 + 8 * ks + tq]);
        uint32_t A3 = fau(sm[O_FI + rh * 36 + 8 * ks + tq + 4]);
        #pragma unroll
        for (int n = 0; n < 4; n++) {
            uint32_t B0 = fau(sm[O_CT + (8 * n + g) * 36 + 8 * ks + tq]);
            uint32_t B1 = fau(sm[O_CT + (8 * n + g) * 36 + 8 * ks + tq + 4]);
            mma8(ag[n], A0, A1, A2, A3, B0, B1);
        }
    }
    #pragma unroll
    for (int n = 0; n < 4; n++) {   // g rows are warp-private
        int f0 = 8 * n + 2 * tq;
        sm[O_G + rl * 36 + f0]     = tf32f(ag[n][0]);
        sm[O_G + rl * 36 + f0 + 1] = tf32f(ag[n][1]);
        sm[O_G + rh * 36 + f0]     = tf32f(ag[n][2]);
        sm[O_G + rh * 36 + f0 + 1] = tf32f(ag[n][3]);
    }
    __syncwarp();

    // ================= beta = g @ fi^T (within own batch, N=64) =================
    float ab[8][4];
    #pragma unroll
    for (int n = 0; n < 8; n++)
        #pragma unroll
        for (int c = 0; c < 4; c++) ab[n][c] = 0.0f;
    #pragma unroll
    for (int ks = 0; ks < 4; ks++) {
        uint32_t A0 = fau(sm[O_G + rl * 36 + 8 * ks + tq]);
        uint32_t A2 = fau(sm[O_G + rl * 36 + 8 * ks + tq + 4]);
        uint32_t A1 = fau(sm[O_G + rh * 36 + 8 * ks + tq]);
        uint32_t A3 = fau(sm[O_G + rh * 36 + 8 * ks + tq + 4]);
        #pragma unroll
        for (int n = 0; n < 8; n++) {
            int jr = bt * 64 + 8 * n + g;
            uint32_t B0 = fau(sm[O_FI + jr * 36 + 8 * ks + tq]);
            uint32_t B1 = fau(sm[O_FI + jr * 36 + 8 * ks + tq + 4]);
            mma8(ab[n], A0, A1, A2, A3, B0, B1);
        }
    }

    // ================= softmax (registers + quad shuffles) =================
    const int jsl = 16 * (w & 3) + g;     // self-col for row rl; rh self = jsl+8
    float mlo = -3.4e38f, mhi = -3.4e38f;
    #pragma unroll
    for (int n = 0; n < 8; n++)
        #pragma unroll
        for (int cc = 0; cc < 2; cc++) {
            int jl = 8 * n + 2 * tq + cc;
            float vlo = ab[n][cc];     if (jl == jsl)     vlo = -3.0e38f;
            float vhi = ab[n][2 + cc]; if (jl == jsl + 8) vhi = -3.0e38f;
            ab[n][cc] = vlo; ab[n][2 + cc] = vhi;
            mlo = fmaxf(mlo, vlo); mhi = fmaxf(mhi, vhi);
        }
    mlo = fmaxf(mlo, __shfl_xor_sync(0xffffffffu, mlo, 1));
    mlo = fmaxf(mlo, __shfl_xor_sync(0xffffffffu, mlo, 2));
    mhi = fmaxf(mhi, __shfl_xor_sync(0xffffffffu, mhi, 1));
    mhi = fmaxf(mhi, __shfl_xor_sync(0xffffffffu, mhi, 2));
    float slo = 0.0f, shi = 0.0f;
    #pragma unroll
    for (int n = 0; n < 8; n++)
        #pragma unroll
        for (int cc = 0; cc < 2; cc++) {
            float elo = __expf(ab[n][cc] - mlo);
            float ehi = __expf(ab[n][2 + cc] - mhi);
            ab[n][cc] = elo; ab[n][2 + cc] = ehi;
            slo += elo; shi += ehi;
        }
    slo += __shfl_xor_sync(0xffffffffu, slo, 1);
    slo += __shfl_xor_sync(0xffffffffu, slo, 2);
    shi += __shfl_xor_sync(0xffffffffu, shi, 1);
    shi += __shfl_xor_sync(0xffffffffu, shi, 2);
    const float rzl = __fdividef(1.0f, slo);
    const float rzh = __fdividef(1.0f, shi);
    #pragma unroll
    for (int n = 0; n < 8; n++)
        #pragma unroll
        for (int cc = 0; cc < 2; cc++) {
            int jl = 8 * n + 2 * tq + cc;
            sm[O_AL + rl * 68 + jl] = tf32f(ab[n][cc] * rzl);
            sm[O_AL + rh * 68 + jl] = tf32f(ab[n][2 + cc] * rzh);
        }
    __syncwarp();   // alpha rows are warp-private

    // ================= v = alpha @ fi (B = fi^T, K=64 own batch) =================
    float av[4][4];
    #pragma unroll
    for (int n = 0; n < 4; n++)
        #pragma unroll
        for (int c = 0; c < 4; c++) av[n][c] = 0.0f;
    #pragma unroll
    for (int ks = 0; ks < 8; ks++) {
        uint32_t A0 = fau(sm[O_AL + rl * 68 + 8 * ks + tq]);
        uint32_t A2 = fau(sm[O_AL + rl * 68 + 8 * ks + tq + 4]);
        uint32_t A1 = fau(sm[O_AL + rh * 68 + 8 * ks + tq]);
        uint32_t A3 = fau(sm[O_AL + rh * 68 + 8 * ks + tq + 4]);
        #pragma unroll
        for (int n = 0; n < 4; n++) {
            uint32_t B0 = fau(sm[O_FIT + (8 * n + g) * 132 + bt * 64 + 8 * ks + tq]);
            uint32_t B1 = fau(sm[O_FIT + (8 * n + g) * 132 + bt * 64 + 8 * ks + tq + 4]);
            mma8(av[n], A0, A1, A2, A3, B0, B1);
        }
    }

    // ================= fc2 + sigmoid =================
    float xlo = 0.0f, xhi = 0.0f;
    #pragma unroll
    for (int n = 0; n < 4; n++)
        #pragma unroll
        for (int cc = 0; cc < 2; cc++) {
            int e = 8 * n + 2 * tq + cc;
            float w2a = sm[O_W2 + e], w2b = sm[O_W2 + 32 + e];
            xlo = fmaf(sm[O_FI + rl * 36 + e], w2a, fmaf(av[n][cc],     w2b, xlo));
            xhi = fmaf(sm[O_FI + rh * 36 + e], w2a, fmaf(av[n][2 + cc], w2b, xhi));
        }
    xlo += __shfl_xor_sync(0xffffffffu, xlo, 1);
    xlo += __shfl_xor_sync(0xffffffffu, xlo, 2);
    xhi += __shfl_xor_sync(0xffffffffu, xhi, 1);
    xhi += __shfl_xor_sync(0xffffffffu, xhi, 2);
    const float bb2 = sm[O_B2];
    if (tq == 0) out[r0 + rl] = __fdividef(1.0f, 1.0f + __expf(-(xlo + bb2)));
    if (tq == 1) out[r0 + rh] = __fdividef(1.0f, 1.0f + __expf(-(xhi + bb2)));
}

extern "C" void kernel_launch(void* const* d_in, const int* in_sizes, int n_in,
                              void* d_out, int out_size) {
    const float* X  = (const float*)d_in[0];
    const float* W1 = (const float*)d_in[1];
    const float* b1 = (const float*)d_in[2];
    const float* C  = (const float*)d_in[3];
    const float* W2 = (const float*)d_in[4];
    const float* b2 = (const float*)d_in[5];
    float* out = (float*)d_out;

    const int rows = in_sizes[0] / 128;   // B*N
    const int nblk = rows / 128;          // 2 batches per CTA

    cudaFuncSetAttribute(attn_mma, cudaFuncAttributeMaxDynamicSharedMemorySize, SMEM_BYTES);
    attn_mma<<<nblk, THREADS, SMEM_BYTES>>>(X, W1, b1, C, W2, b2, out);
}

// round 5
// speedup vs baseline: 6.1843x; 1.8848x over previous
#include <cuda_runtime.h>
#include <cuda_fp16.h>
#include <cstdint>
#include <cstddef>

#define THREADS 256

// ---- dynamic smem byte offsets ----
// phase A: X [128 rows x 288B] @0
// phase B (aliases X): G [128 x 96B] @0 ; AL [128 x 160B] @12288 (ends 32768)
#define O_X    0u
#define O_G    0u
#define O_AL   12288u
#define O_W1T  36864u   // 32 x 288B
#define O_CT   46080u   // 32 x 96B
#define O_FI   49152u   // 128 x 96B
#define O_FIT  61440u   // 32 x 288B
#define O_B1   70656u   // 32 f32
#define O_W2   70784u   // 64 f32
#define O_B2   71040u   // 1 f32
#define SMEM_BYTES 71072u

#define CP_ASYNC16(d, s) asm volatile("cp.async.cg.shared.global [%0], [%1], 16;" :: "r"(d), "l"(s))
#define CP_COMMIT()      asm volatile("cp.async.commit_group;")
#define CP_WAIT0()       asm volatile("cp.async.wait_group 0;")

// prep buffer: W1T-half (9216B, 32 rows x 288B) + CT-half (3072B, 32 rows x 96B)
__device__ __align__(16) unsigned char g_prep[12288];

// k-unit permutation within a 16-element (8 half2-unit) group:
// unit u -> pos 2*(u&3) + (u>>2). Makes (k=2t, k=2t+8) half2 pairs adjacent -> LDS.64 frags.
__device__ __host__ __forceinline__ int posu(int u) { return 2 * (u & 3) + (u >> 2); }

// D(16x8 f32) += A(16x16 f16) * B(8x16 f16)  [row.col]
__device__ __forceinline__ void mma16(float* d, uint32_t a0, uint32_t a1, uint32_t a2, uint32_t a3,
                                      uint32_t b0, uint32_t b1) {
    asm("mma.sync.aligned.m16n8k16.row.col.f32.f16.f16.f32 "
        "{%0,%1,%2,%3}, {%4,%5,%6,%7}, {%8,%9}, {%0,%1,%2,%3};"
        : "+f"(d[0]), "+f"(d[1]), "+f"(d[2]), "+f"(d[3])
        : "r"(a0), "r"(a1), "r"(a2), "r"(a3), "r"(b0), "r"(b1));
}

__global__ void prep_kernel(const float* __restrict__ W1, const float* __restrict__ C) {
    const int tid = threadIdx.x;
    // W1T[e][k] half, k permuted in 16-groups, pitch 288B
    for (int idx = tid; idx < 4096; idx += 256) {
        int e = idx & 31, k = idx >> 5;           // W1 is [k][e]
        int off = e * 288 + (k >> 4) * 32 + posu((k >> 1) & 7) * 4 + (k & 1) * 2;
        *(half*)(g_prep + off) = __float2half_rn(W1[idx]);
    }
    // CT[f][e] half, e permuted, pitch 96B
    for (int idx = tid; idx < 1024; idx += 256) {
        int f = idx & 31, e = idx >> 5;           // C is [e][f]
        int off = 9216 + f * 96 + (e >> 4) * 32 + posu((e >> 1) & 7) * 4 + (e & 1) * 2;
        *(half*)(g_prep + off) = __float2half_rn(C[idx]);
    }
}

__global__ void __launch_bounds__(THREADS, 3) attn_h(
    const float* __restrict__ X, const float* __restrict__ b1g,
    const float* __restrict__ W2g, const float* __restrict__ b2g,
    float* __restrict__ out)
{
    extern __shared__ __align__(16) char sm[];
    const int tid = threadIdx.x;
    const int w   = tid >> 5;
    const int l   = tid & 31;
    const int g   = l >> 2;          // 0..7
    const int tq  = l & 3;           // 0..3
    const int m0  = w * 16;
    const int bt  = w >> 2;          // batch within CTA
    const int rl  = m0 + g, rh = rl + 8;
    const size_t r0 = (size_t)blockIdx.x * 128;

    // ---- pull prepped W1T+CT (contiguous 12288B -> smem @ O_W1T) ----
    {
        uint32_t dst = (uint32_t)__cvta_generic_to_shared(sm + O_W1T) + tid * 16;
        const unsigned char* src = g_prep + tid * 16;
        CP_ASYNC16(dst, src);
        CP_ASYNC16(dst + 4096, src + 4096);
        CP_ASYNC16(dst + 8192, src + 8192);
        CP_COMMIT();
    }
    // ---- params (f32) ----
    if (tid < 32) *(float*)(sm + O_B1 + tid * 4) = b1g[tid];
    if (tid < 64) *(float*)(sm + O_W2 + tid * 4) = W2g[tid];
    if (tid == 0) *(float*)(sm + O_B2) = b2g[0];

    // ---- stage X as half, permuted, pitch 288B ----
    {
        const float4* X4 = (const float4*)(X + r0 * 128);
        #pragma unroll
        for (int i = 0; i < 16; i++) {
            int idx = tid + i * 256;              // 0..4095
            int row = idx >> 5, q = idx & 31;     // float4 q -> units 2q, 2q+1
            float4 xv = X4[idx];
            int u0 = 2 * q, u1 = u0 + 1;
            *(half2*)(sm + O_X + row * 288 + (u0 >> 3) * 32 + posu(u0 & 7) * 4) =
                __floats2half2_rn(xv.x, xv.y);
            *(half2*)(sm + O_X + row * 288 + (u1 >> 3) * 32 + posu(u1 & 7) * 4) =
                __floats2half2_rn(xv.z, xv.w);
        }
    }
    CP_WAIT0();
    __syncthreads();

    // ================= fc1: acc = X @ W1 (K=128, 8 k16 blocks) =================
    float acc[4][4];
    #pragma unroll
    for (int n = 0; n < 4; n++) { acc[n][0]=acc[n][1]=acc[n][2]=acc[n][3]=0.0f; }
    #pragma unroll
    for (int blk = 0; blk < 8; blk++) {
        uint2 al = *(const uint2*)(sm + O_X + rl * 288 + blk * 32 + 8 * tq);
        uint2 ah = *(const uint2*)(sm + O_X + rh * 288 + blk * 32 + 8 * tq);
        #pragma unroll
        for (int n = 0; n < 4; n++) {
            uint2 b = *(const uint2*)(sm + O_W1T + (8 * n + g) * 288 + blk * 32 + 8 * tq);
            mma16(acc[n], al.x, ah.x, al.y, ah.y, b.x, b.y);
        }
    }

    // ---- epilogue: fi = relu(acc + b1) -> FI [i][e-perm], FIT [e][i-perm] ----
    const int fitL = ((rl >> 4) * 32 + posu((rl >> 1) & 7) * 4 + (rl & 1) * 2);
    const int fitH = ((rh >> 4) * 32 + posu((rh >> 1) & 7) * 4 + (rh & 1) * 2);
    #pragma unroll
    for (int n = 0; n < 4; n++) {
        int e0 = 8 * n + 2 * tq;
        float b0 = *(const float*)(sm + O_B1 + e0 * 4);
        float b1v = *(const float*)(sm + O_B1 + (e0 + 1) * 4);
        half2 hlo = __floats2half2_rn(fmaxf(acc[n][0] + b0, 0.0f), fmaxf(acc[n][1] + b1v, 0.0f));
        half2 hhi = __floats2half2_rn(fmaxf(acc[n][2] + b0, 0.0f), fmaxf(acc[n][3] + b1v, 0.0f));
        int coff = (n >> 1) * 32 + (2 * tq + (n & 1)) * 4;
        *(half2*)(sm + O_FI + rl * 96 + coff) = hlo;
        *(half2*)(sm + O_FI + rh * 96 + coff) = hhi;
        *(half*)(sm + O_FIT + e0 * 288 + fitL)       = __low2half(hlo);
        *(half*)(sm + O_FIT + (e0 + 1) * 288 + fitL) = __high2half(hlo);
        *(half*)(sm + O_FIT + e0 * 288 + fitH)       = __low2half(hhi);
        *(half*)(sm + O_FIT + (e0 + 1) * 288 + fitH) = __high2half(hhi);
    }
    __syncthreads();   // FI/FIT visible; X region dead -> reuse as G/AL

    // ================= g = fi @ C (K=32) =================
    float ag[4][4];
    #pragma unroll
    for (int n = 0; n < 4; n++) { ag[n][0]=ag[n][1]=ag[n][2]=ag[n][3]=0.0f; }
    #pragma unroll
    for (int blk = 0; blk < 2; blk++) {
        uint2 al = *(const uint2*)(sm + O_FI + rl * 96 + blk * 32 + 8 * tq);
        uint2 ah = *(const uint2*)(sm + O_FI + rh * 96 + blk * 32 + 8 * tq);
        #pragma unroll
        for (int n = 0; n < 4; n++) {
            uint2 b = *(const uint2*)(sm + O_CT + (8 * n + g) * 96 + blk * 32 + 8 * tq);
            mma16(ag[n], al.x, ah.x, al.y, ah.y, b.x, b.y);
        }
    }
    #pragma unroll
    for (int n = 0; n < 4; n++) {    // g rows are warp-private
        int coff = (n >> 1) * 32 + (2 * tq + (n & 1)) * 4;
        *(half2*)(sm + O_G + rl * 96 + coff) = __floats2half2_rn(ag[n][0], ag[n][1]);
        *(half2*)(sm + O_G + rh * 96 + coff) = __floats2half2_rn(ag[n][2], ag[n][3]);
    }
    __syncwarp();

    // ================= beta = g @ fi^T (own batch, N=64, K=32) =================
    float ab[8][4];
    #pragma unroll
    for (int n = 0; n < 8; n++) { ab[n][0]=ab[n][1]=ab[n][2]=ab[n][3]=0.0f; }
    #pragma unroll
    for (int blk = 0; blk < 2; blk++) {
        uint2 al = *(const uint2*)(sm + O_G + rl * 96 + blk * 32 + 8 * tq);
        uint2 ah = *(const uint2*)(sm + O_G + rh * 96 + blk * 32 + 8 * tq);
        #pragma unroll
        for (int n = 0; n < 8; n++) {
            uint2 b = *(const uint2*)(sm + O_FI + (bt * 64 + 8 * n + g) * 96 + blk * 32 + 8 * tq);
            mma16(ab[n], al.x, ah.x, al.y, ah.y, b.x, b.y);
        }
    }

    // ================= softmax (registers + quad shuffles) =================
    const int jsl = 16 * (w & 3) + g;           // self col for rl; rh self = jsl+8
    float mlo = -3.4e38f, mhi = -3.4e38f;
    #pragma unroll
    for (int n = 0; n < 8; n++)
        #pragma unroll
        for (int cc = 0; cc < 2; cc++) {
            int jl = 8 * n + 2 * tq + cc;
            float vlo = ab[n][cc];     if (jl == jsl)     vlo = -3.0e38f;
            float vhi = ab[n][2 + cc]; if (jl == jsl + 8) vhi = -3.0e38f;
            ab[n][cc] = vlo; ab[n][2 + cc] = vhi;
            mlo = fmaxf(mlo, vlo); mhi = fmaxf(mhi, vhi);
        }
    mlo = fmaxf(mlo, __shfl_xor_sync(0xffffffffu, mlo, 1));
    mlo = fmaxf(mlo, __shfl_xor_sync(0xffffffffu, mlo, 2));
    mhi = fmaxf(mhi, __shfl_xor_sync(0xffffffffu, mhi, 1));
    mhi = fmaxf(mhi, __shfl_xor_sync(0xffffffffu, mhi, 2));
    float slo = 0.0f, shi = 0.0f;
    #pragma unroll
    for (int n = 0; n < 8; n++)
        #pragma unroll
        for (int cc = 0; cc < 2; cc++) {
            float elo = __expf(ab[n][cc] - mlo);
            float ehi = __expf(ab[n][2 + cc] - mhi);
            ab[n][cc] = elo; ab[n][2 + cc] = ehi;
            slo += elo; shi += ehi;
        }
    slo += __shfl_xor_sync(0xffffffffu, slo, 1);
    slo += __shfl_xor_sync(0xffffffffu, slo, 2);
    shi += __shfl_xor_sync(0xffffffffu, shi, 1);
    shi += __shfl_xor_sync(0xffffffffu, shi, 2);
    const float rzl = __fdividef(1.0f, slo);
    const float rzh = __fdividef(1.0f, shi);
    #pragma unroll
    for (int n = 0; n < 8; n++) {    // alpha rows are warp-private, half2, j-perm
        int coff = (n >> 1) * 32 + (2 * tq + (n & 1)) * 4;
        *(half2*)(sm + O_AL + rl * 160 + coff) = __floats2half2_rn(ab[n][0] * rzl, ab[n][1] * rzl);
        *(half2*)(sm + O_AL + rh * 160 + coff) = __floats2half2_rn(ab[n][2] * rzh, ab[n][3] * rzh);
    }
    __syncwarp();

    // ================= v = alpha @ fi (K=64, B = FIT) =================
    float av[4][4];
    #pragma unroll
    for (int n = 0; n < 4; n++) { av[n][0]=av[n][1]=av[n][2]=av[n][3]=0.0f; }
    #pragma unroll
    for (int lb = 0; lb < 4; lb++) {
        uint2 al = *(const uint2*)(sm + O_AL + rl * 160 + lb * 32 + 8 * tq);
        uint2 ah = *(const uint2*)(sm + O_AL + rh * 160 + lb * 32 + 8 * tq);
        #pragma unroll
        for (int n = 0; n < 4; n++) {
            uint2 b = *(const uint2*)(sm + O_FIT + (8 * n + g) * 288 + (bt * 4 + lb) * 32 + 8 * tq);
            mma16(av[n], al.x, ah.x, al.y, ah.y, b.x, b.y);
        }
    }

    // ================= fc2 + sigmoid =================
    float xlo = 0.0f, xhi = 0.0f;
    #pragma unroll
    for (int n = 0; n < 4; n++) {
        int e0 = 8 * n + 2 * tq;
        int coff = (n >> 1) * 32 + (2 * tq + (n & 1)) * 4;
        half2 flo = *(const half2*)(sm + O_FI + rl * 96 + coff);
        half2 fhi = *(const half2*)(sm + O_FI + rh * 96 + coff);
        float w2a0 = *(const float*)(sm + O_W2 + e0 * 4);
        float w2a1 = *(const float*)(sm + O_W2 + (e0 + 1) * 4);
        float w2b0 = *(const float*)(sm + O_W2 + (32 + e0) * 4);
        float w2b1 = *(const float*)(sm + O_W2 + (33 + e0) * 4);
        xlo = fmaf(__low2float(flo), w2a0, fmaf(__high2float(flo), w2a1,
              fmaf(av[n][0], w2b0, fmaf(av[n][1], w2b1, xlo))));
        xhi = fmaf(__low2float(fhi), w2a0, fmaf(__high2float(fhi), w2a1,
              fmaf(av[n][2], w2b0, fmaf(av[n][3], w2b1, xhi))));
    }
    xlo += __shfl_xor_sync(0xffffffffu, xlo, 1);
    xlo += __shfl_xor_sync(0xffffffffu, xlo, 2);
    xhi += __shfl_xor_sync(0xffffffffu, xhi, 1);
    xhi += __shfl_xor_sync(0xffffffffu, xhi, 2);
    const float bb2 = *(const float*)(sm + O_B2);
    if (tq == 0) out[r0 + rl] = __fdividef(1.0f, 1.0f + __expf(-(xlo + bb2)));
    if (tq == 1) out[r0 + rh] = __fdividef(1.0f, 1.0f + __expf(-(xhi + bb2)));
}

extern "C" void kernel_launch(void* const* d_in, const int* in_sizes, int n_in,
                              void* d_out, int out_size) {
    const float* X  = (const float*)d_in[0];
    const float* W1 = (const float*)d_in[1];
    const float* b1 = (const float*)d_in[2];
    const float* C  = (const float*)d_in[3];
    const float* W2 = (const float*)d_in[4];
    const float* b2 = (const float*)d_in[5];
    float* out = (float*)d_out;

    const int rows = in_sizes[0] / 128;   // B*N
    const int nblk = rows / 128;          // 2 batches per CTA

    prep_kernel<<<1, 256>>>(W1, C);
    cudaFuncSetAttribute(attn_h, cudaFuncAttributeMaxDynamicSharedMemorySize, SMEM_BYTES);
    attn_h<<<nblk, THREADS, SMEM_BYTES>>>(X, b1, W2, b2, out);
}